// round 12
// baseline (speedup 1.0000x reference)
#include <cuda_runtime.h>

#define C_DIM   64
#define NKER    32
#define BEVX    256
#define BEVY    256
#define NBATCH  4
#define CELLS   (NBATCH * BEVX * BEVY)      // 262144
#define MAXN    131072
#define PPB     128
#define ZCAP    4096                         // slots per z
#define NSB     4                            // sub-buckets per z
#define SBCAP   1024                         // slots per sub-bucket
#define NTILES  (NKER * NSB * (SBCAP / PPB)) // 32*4*8 = 1024
#define CGRID   592                          // 4/SM x 148
#define SGRID   512                          // scatter: 512*256 >= N

// ---------------- device state (zero/static-init at module load) ------------
// Invariant maintained across graph replays: scratch rows and touched map are
// zero at scatter time (transpose re-zeroes what it consumed); cursors hold
// their bucket bases (transpose block 0 resets them); g_extra == 0.
__device__ float4        g_scratch4[(size_t)CELLS * C_DIM / 4]; // 67 MB, zeroed
__device__ unsigned char g_touched[CELLS];                      // zeroed
__device__ unsigned      g_sorted[MAXN];     // stale-ok (count-guarded)
__device__ unsigned      g_cells[MAXN];      // stale-ok (count-guarded)
__device__ unsigned      g_extra;            // compute tile ticket
#define SB4(z) (z)*ZCAP, (z)*ZCAP+SBCAP, (z)*ZCAP+2*SBCAP, (z)*ZCAP+3*SBCAP
__device__ int g_cursor[NKER * NSB] = {
    SB4(0),  SB4(1),  SB4(2),  SB4(3),  SB4(4),  SB4(5),  SB4(6),  SB4(7),
    SB4(8),  SB4(9),  SB4(10), SB4(11), SB4(12), SB4(13), SB4(14), SB4(15),
    SB4(16), SB4(17), SB4(18), SB4(19), SB4(20), SB4(21), SB4(22), SB4(23),
    SB4(24), SB4(25), SB4(26), SB4(27), SB4(28), SB4(29), SB4(30), SB4(31)
};

#define SCRATCH ((float*)g_scratch4)

// ---------------- packed fp32x2 helpers -------------------------------------
__device__ __forceinline__ unsigned long long pk(float x, float y) {
    unsigned long long r;
    asm("mov.b64 %0, {%1, %2};" : "=l"(r) : "f"(x), "f"(y));
    return r;
}
__device__ __forceinline__ float2 upk(unsigned long long v) {
    float2 r;
    asm("mov.b64 {%0, %1}, %2;" : "=f"(r.x), "=f"(r.y) : "l"(v));
    return r;
}
__device__ __forceinline__ unsigned long long ffma2(unsigned long long a,
                                                    unsigned long long b,
                                                    unsigned long long c) {
    unsigned long long d;
    asm("fma.rn.f32x2 %0, %1, %2, %3;" : "=l"(d) : "l"(a), "l"(b), "l"(c));
    return d;
}
__device__ __forceinline__ void red_v2(float* p, float a, float b) {
    asm volatile("red.global.add.v2.f32 [%0], {%1, %2};"
                 :: "l"(p), "f"(a), "f"(b) : "memory");
}

// ---------------- coord access ----------------------------------------------
// int64 coords: odd 32-bit words are zero high-words. int32: w[3]=b[0]=3 != 0.
__device__ __forceinline__ int detect64(const void* coords) {
    const unsigned* w = (const unsigned*)coords;
    return (w[1] | w[3] | w[5] | w[7]) == 0u;
}
__device__ __forceinline__ void ld_zcell(const void* coords, int n, int is64,
                                         int& z, int& cell) {
    int x, y, b;
    if (is64) {
        const long long* p = (const long long*)coords + 4ll * n;
        x = (int)p[0]; z = (int)p[1]; y = (int)p[2]; b = (int)p[3];
    } else {
        const int* p = (const int*)coords + 4 * n;
        x = p[0]; z = p[1]; y = p[2]; b = p[3];
    }
    // defensive clamps: never let malformed input index outside our arrays
    z    = z & (NKER - 1);
    cell = ((b * BEVX + x) * BEVY + y) & (CELLS - 1);
}

// ---------------- kernel 1: bucket scatter (single pass, no barrier) --------
__global__ void __launch_bounds__(256) k_scatter(const void* __restrict__ coords,
                                                 int N) {
    __shared__ int s_is64;
    if (threadIdx.x == 0) s_is64 = detect64(coords);
    __syncthreads();
    int is64 = s_is64;
    int sb   = (blockIdx.x + (threadIdx.x >> 5)) & (NSB - 1);

    for (int n = blockIdx.x * 256 + threadIdx.x; n < N; n += SGRID * 256) {
        int z, cell;
        ld_zcell(coords, n, is64, z, cell);
        int ci  = z * NSB + sb;
        int pos = atomicAdd(&g_cursor[ci], 1);
        if (pos < (z * NSB + sb + 1) * SBCAP) {  // overflow guard (8.7 sigma)
            g_sorted[pos]   = (unsigned)n;
            g_cells[pos]    = (unsigned)cell;
            g_touched[cell] = 1;
        }
    }
}

// ---------------- kernel 2: persistent broadcast-layout GEMM + RED.v2 -------
// Tile = 128 slots of one sub-bucket; valid count from final cursor value.
// Warp owns 16 points, lane = channel-pair; kernel matrix via __ldg (L1-hot).
__global__ void __launch_bounds__(256, 4) k_compute(const float* __restrict__ feat,
                                                    const float* __restrict__ ker) {
    __shared__ float sfeat[128 * 64];        // [p][c] 32KB
    __shared__ unsigned s_next;
    int tid  = threadIdx.x;
    int lane = tid & 31;
    int w    = tid >> 5;
    int p0   = w * 16;

    int tile = blockIdx.x;
    while (tile < NTILES) {
        int sbg = tile >> 3;                 // sub-bucket 0..127
        int tt  = tile & 7;                  // tile within sub-bucket
        int cnt = g_cursor[sbg] - sbg * SBCAP;
        if (cnt > SBCAP) cnt = SBCAP;
        if (cnt < 0)     cnt = 0;
        int valid = cnt - tt * PPB;
        if (valid > PPB) valid = PPB;

        if (valid > 0) {
            int base = sbg * SBCAP + tt * PPB;
            const unsigned long long* kz =
                (const unsigned long long*)(ker + (size_t)(sbg >> 2) * 4096);

            // coalesced feature gather: 16 lanes cover one 256B row
            #pragma unroll
            for (int q = 0; q < 8; q++) {
                int idx = tid + 256 * q;
                int p   = idx >> 4;
                int c4  = idx & 15;
                float4 v = make_float4(0.f, 0.f, 0.f, 0.f);
                if (p < valid) {
                    unsigned pv = __ldg(&g_sorted[base + p]) & (MAXN - 1u);
                    v = *(const float4*)(feat + (size_t)pv * 64 + 4 * c4);
                }
                *(float4*)&sfeat[p * 64 + 4 * c4] = v;
            }
            __syncthreads();

            unsigned long long acc[16];
            #pragma unroll
            for (int s = 0; s < 16; s++) acc[s] = 0ull;

            #pragma unroll 2
            for (int j4 = 0; j4 < 16; j4++) {
                unsigned long long k0 = __ldg(&kz[(4 * j4 + 0) * 32 + lane]);
                unsigned long long k1 = __ldg(&kz[(4 * j4 + 1) * 32 + lane]);
                unsigned long long k2 = __ldg(&kz[(4 * j4 + 2) * 32 + lane]);
                unsigned long long k3 = __ldg(&kz[(4 * j4 + 3) * 32 + lane]);
                #pragma unroll
                for (int s = 0; s < 16; s++) {
                    float4 f4 = *(const float4*)&sfeat[(p0 + s) * 64 + 4 * j4];
                    unsigned long long a = acc[s];
                    a = ffma2(pk(f4.x, f4.x), k0, a);
                    a = ffma2(pk(f4.y, f4.y), k1, a);
                    a = ffma2(pk(f4.z, f4.z), k2, a);
                    a = ffma2(pk(f4.w, f4.w), k3, a);
                    acc[s] = a;
                }
            }

            #pragma unroll
            for (int s = 0; s < 16; s++) {
                if (p0 + s < valid) {
                    unsigned cell = __ldg(&g_cells[base + p0 + s]) & (CELLS - 1u);
                    float2 v = upk(acc[s]);
                    red_v2(SCRATCH + (size_t)cell * C_DIM + 2 * lane, v.x, v.y);
                }
            }
        }

        // next tile via drain-only ticket (sync also fences sfeat reuse)
        if (tid == 0) s_next = (unsigned)gridDim.x + atomicAdd(&g_extra, 1u);
        __syncthreads();
        tile = (int)s_next;
    }
}

// ---------------- kernel 3: transpose + state cleanup -----------------------
// 256-thread blocks, 64y x 64c tile. Re-zeroes consumed scratch rows and
// touched bytes; block 0 resets cursors + ticket for the next replay.
__global__ void __launch_bounds__(256) k_transpose(float* __restrict__ out) {
    __shared__ __align__(16) float ts[64 * 68];
    __shared__ unsigned char s_t[64];
    int bid = blockIdx.x;                // b(4) x x(256) x yq(4)
    int yq  = bid & 3;
    int x   = (bid >> 2) & 255;
    int b   = bid >> 10;
    int t   = threadIdx.x;

    int cellbase = (b * BEVX + x) * BEVY + yq * 64;
    if (t < 64) s_t[t] = g_touched[cellbase + t];
    __syncthreads();
    if (t < 64 && s_t[t]) g_touched[cellbase + t] = 0;   // clear for next replay
    if (bid == 0) {                                       // reset cursors/ticket
        if (t < NKER * NSB)
            g_cursor[t] = (t >> 2) * ZCAP + (t & 3) * SBCAP;
        if (t == 128) g_extra = 0;
    }

    float4* src4 = (float4*)(SCRATCH + (size_t)cellbase * C_DIM);
    float4  z4   = make_float4(0.f, 0.f, 0.f, 0.f);
    #pragma unroll
    for (int it = 0; it < 4; it++) {
        int i  = t + 256 * it;           // 0..1023
        int y  = i >> 4;
        int c4 = i & 15;
        float4 v = z4;
        if (s_t[y]) {
            v = src4[i];
            src4[i] = z4;                // re-zero consumed scratch row
        }
        *(float4*)&ts[y * 68 + 4 * c4] = v;
    }
    __syncthreads();

    int c  = t >> 2;                     // 0..63
    int gq = t & 3;
    float4* out4 = (float4*)out;
    // (b,c) plane = 16384 float4; x row = 64 float4; y-quarter = 16 float4
    size_t rowbase = ((size_t)(b * C_DIM + c)) * 16384 + x * 64 + yq * 16;
    #pragma unroll
    for (int it = 0; it < 4; it++) {
        int g = gq + 4 * it;             // 0..15 float4 within 64 y's
        float4 v;
        v.x = ts[(4 * g + 0) * 68 + c];
        v.y = ts[(4 * g + 1) * 68 + c];
        v.z = ts[(4 * g + 2) * 68 + c];
        v.w = ts[(4 * g + 3) * 68 + c];
        out4[rowbase + g] = v;
    }
}

// ---------------- launcher ---------------------------------------------------
extern "C" void kernel_launch(void* const* d_in, const int* in_sizes, int n_in,
                              void* d_out, int out_size) {
    const float* feat   = (const float*)d_in[0];
    const float* ker    = (const float*)d_in[1];
    const void*  coords = d_in[2];
    int N = in_sizes[0] / C_DIM;

    k_scatter<<<SGRID, 256>>>(coords, N);
    k_compute<<<CGRID, 256>>>(feat, ker);
    k_transpose<<<4 * NBATCH * BEVX, 256>>>((float*)d_out);
}

// round 13
// speedup vs baseline: 1.2795x; 1.2795x over previous
#include <cuda_runtime.h>

#define C_DIM   64
#define NKER    32
#define BEVX    256
#define BEVY    256
#define NBATCH  4
#define CELLS   (NBATCH * BEVX * BEVY)      // 262144
#define MAXN    131072
#define PPB     128
#define ZCAP    4096                         // slots per z
#define NSB     4                            // sub-buckets per z
#define SBCAP   1024                         // slots per sub-bucket
#define NTILES  (NKER * NSB * (SBCAP / PPB)) // 1024
#define CGRID   592                          // 4/SM x 148
#define SGRID   128                          // scatter: 128 x 1024 = 131072 >= N
#define STHREADS 1024

// ---------------- device state (zero/static-init at module load) ------------
// Invariant across graph replays: scratch rows + touched map zero at scatter
// time (transpose re-zeroes what it consumed); cursors hold bucket bases
// (transpose block 0 resets); g_extra == 0.
__device__ float4        g_scratch4[(size_t)CELLS * C_DIM / 4]; // 67 MB, zeroed
__device__ unsigned char g_touched[CELLS];                      // zeroed
__device__ unsigned      g_sorted[MAXN];     // stale-ok (count-guarded)
__device__ unsigned      g_cells[MAXN];      // stale-ok (count-guarded)
__device__ unsigned      g_extra;            // compute tile ticket
#define SB4(z) (z)*ZCAP, (z)*ZCAP+SBCAP, (z)*ZCAP+2*SBCAP, (z)*ZCAP+3*SBCAP
__device__ int g_cursor[NKER * NSB] = {
    SB4(0),  SB4(1),  SB4(2),  SB4(3),  SB4(4),  SB4(5),  SB4(6),  SB4(7),
    SB4(8),  SB4(9),  SB4(10), SB4(11), SB4(12), SB4(13), SB4(14), SB4(15),
    SB4(16), SB4(17), SB4(18), SB4(19), SB4(20), SB4(21), SB4(22), SB4(23),
    SB4(24), SB4(25), SB4(26), SB4(27), SB4(28), SB4(29), SB4(30), SB4(31)
};

#define SCRATCH ((float*)g_scratch4)

// ---------------- packed fp32x2 helpers -------------------------------------
__device__ __forceinline__ unsigned long long pk(float x, float y) {
    unsigned long long r;
    asm("mov.b64 %0, {%1, %2};" : "=l"(r) : "f"(x), "f"(y));
    return r;
}
__device__ __forceinline__ float2 upk(unsigned long long v) {
    float2 r;
    asm("mov.b64 {%0, %1}, %2;" : "=f"(r.x), "=f"(r.y) : "l"(v));
    return r;
}
__device__ __forceinline__ unsigned long long ffma2(unsigned long long a,
                                                    unsigned long long b,
                                                    unsigned long long c) {
    unsigned long long d;
    asm("fma.rn.f32x2 %0, %1, %2, %3;" : "=l"(d) : "l"(a), "l"(b), "l"(c));
    return d;
}
__device__ __forceinline__ void red_v2(float* p, float a, float b) {
    asm volatile("red.global.add.v2.f32 [%0], {%1, %2};"
                 :: "l"(p), "f"(a), "f"(b) : "memory");
}

// ---------------- coord access ----------------------------------------------
// int64 coords: odd 32-bit words are zero high-words. int32: w[3]=b[0]=3 != 0.
__device__ __forceinline__ int detect64(const void* coords) {
    const unsigned* w = (const unsigned*)coords;
    return (w[1] | w[3] | w[5] | w[7]) == 0u;
}
__device__ __forceinline__ void ld_zcell(const void* coords, int n, int is64,
                                         int& z, int& cell) {
    int x, y, b;
    if (is64) {
        const long long* p = (const long long*)coords + 4ll * n;
        x = (int)p[0]; z = (int)p[1]; y = (int)p[2]; b = (int)p[3];
    } else {
        const int* p = (const int*)coords + 4 * n;
        x = p[0]; z = p[1]; y = p[2]; b = p[3];
    }
    // defensive clamps: malformed input can never index outside our arrays
    z    = z & (NKER - 1);
    cell = ((b * BEVX + x) * BEVY + y) & (CELLS - 1);
}

// ---------------- kernel 1: block-aggregated two-level scatter --------------
// One point per thread. Local rank via smem counters (32 per block), ONE
// global atomic per (block, z) -> 32-op chains per cursor instead of 780.
__global__ void __launch_bounds__(STHREADS) k_scatter(const void* __restrict__ coords,
                                                      int N) {
    __shared__ int s_cnt[NKER];
    __shared__ int s_base[NKER];
    __shared__ int s_is64;
    int tid = threadIdx.x;
    if (tid == 0) s_is64 = detect64(coords);
    if (tid < NKER) s_cnt[tid] = 0;
    __syncthreads();

    int sb = blockIdx.x & (NSB - 1);
    int n  = blockIdx.x * STHREADS + tid;
    bool valid = n < N;
    int z = 0, cell = 0, rank = 0;
    if (valid) {
        ld_zcell(coords, n, s_is64, z, cell);
        rank = atomicAdd(&s_cnt[z], 1);          // local rank (smem)
    }
    __syncthreads();

    if (tid < NKER && s_cnt[tid] > 0)            // one global atomic per z
        s_base[tid] = atomicAdd(&g_cursor[tid * NSB + sb], s_cnt[tid]);
    __syncthreads();

    if (valid) {
        int pos = s_base[z] + rank;
        if (pos < (z * NSB + sb + 1) * SBCAP) {  // +8.8 sigma overflow guard
            g_sorted[pos]   = (unsigned)n;       // contiguous per-bucket runs
            g_cells[pos]    = (unsigned)cell;
            g_touched[cell] = 1;
        }
    }
}

// ---------------- kernel 2: persistent broadcast-layout GEMM + RED.v2 -------
// Tile = 128 slots of one sub-bucket; valid count from final cursor value.
// Warp owns 16 points, lane = channel-pair; kernel matrix via __ldg (L1-hot).
__global__ void __launch_bounds__(256, 4) k_compute(const float* __restrict__ feat,
                                                    const float* __restrict__ ker) {
    __shared__ float sfeat[128 * 64];        // [p][c] 32KB
    __shared__ unsigned s_next;
    int tid  = threadIdx.x;
    int lane = tid & 31;
    int w    = tid >> 5;
    int p0   = w * 16;

    int tile = blockIdx.x;
    while (tile < NTILES) {
        int sbg = tile >> 3;                 // sub-bucket 0..127
        int tt  = tile & 7;                  // tile within sub-bucket
        int cnt = g_cursor[sbg] - sbg * SBCAP;
        if (cnt > SBCAP) cnt = SBCAP;
        if (cnt < 0)     cnt = 0;
        int valid = cnt - tt * PPB;
        if (valid > PPB) valid = PPB;

        if (valid > 0) {
            int base = sbg * SBCAP + tt * PPB;
            const unsigned long long* kz =
                (const unsigned long long*)(ker + (size_t)(sbg >> 2) * 4096);

            // coalesced feature gather: 16 lanes cover one 256B row
            #pragma unroll
            for (int q = 0; q < 8; q++) {
                int idx = tid + 256 * q;
                int p   = idx >> 4;
                int c4  = idx & 15;
                float4 v = make_float4(0.f, 0.f, 0.f, 0.f);
                if (p < valid) {
                    unsigned pv = __ldg(&g_sorted[base + p]) & (MAXN - 1u);
                    v = *(const float4*)(feat + (size_t)pv * 64 + 4 * c4);
                }
                *(float4*)&sfeat[p * 64 + 4 * c4] = v;
            }
            __syncthreads();

            unsigned long long acc[16];
            #pragma unroll
            for (int s = 0; s < 16; s++) acc[s] = 0ull;

            #pragma unroll 2
            for (int j4 = 0; j4 < 16; j4++) {
                unsigned long long k0 = __ldg(&kz[(4 * j4 + 0) * 32 + lane]);
                unsigned long long k1 = __ldg(&kz[(4 * j4 + 1) * 32 + lane]);
                unsigned long long k2 = __ldg(&kz[(4 * j4 + 2) * 32 + lane]);
                unsigned long long k3 = __ldg(&kz[(4 * j4 + 3) * 32 + lane]);
                #pragma unroll
                for (int s = 0; s < 16; s++) {
                    float4 f4 = *(const float4*)&sfeat[(p0 + s) * 64 + 4 * j4];
                    unsigned long long a = acc[s];
                    a = ffma2(pk(f4.x, f4.x), k0, a);
                    a = ffma2(pk(f4.y, f4.y), k1, a);
                    a = ffma2(pk(f4.z, f4.z), k2, a);
                    a = ffma2(pk(f4.w, f4.w), k3, a);
                    acc[s] = a;
                }
            }

            #pragma unroll
            for (int s = 0; s < 16; s++) {
                if (p0 + s < valid) {
                    unsigned cell = __ldg(&g_cells[base + p0 + s]) & (CELLS - 1u);
                    float2 v = upk(acc[s]);
                    red_v2(SCRATCH + (size_t)cell * C_DIM + 2 * lane, v.x, v.y);
                }
            }
        }

        // next tile via drain-only ticket (sync also fences sfeat reuse)
        if (tid == 0) s_next = (unsigned)gridDim.x + atomicAdd(&g_extra, 1u);
        __syncthreads();
        tile = (int)s_next;
    }
}

// ---------------- kernel 3: transpose + state cleanup -----------------------
// 256-thread blocks, 64y x 64c tile. Re-zeroes consumed scratch rows and
// touched bytes; block 0 resets cursors + ticket for the next replay.
__global__ void __launch_bounds__(256) k_transpose(float* __restrict__ out) {
    __shared__ __align__(16) float ts[64 * 68];
    __shared__ unsigned char s_t[64];
    int bid = blockIdx.x;                // b(4) x x(256) x yq(4)
    int yq  = bid & 3;
    int x   = (bid >> 2) & 255;
    int b   = bid >> 10;
    int t   = threadIdx.x;

    int cellbase = (b * BEVX + x) * BEVY + yq * 64;
    if (t < 64) s_t[t] = g_touched[cellbase + t];
    __syncthreads();
    if (t < 64 && s_t[t]) g_touched[cellbase + t] = 0;   // clear for next replay
    if (bid == 0) {                                       // reset cursors/ticket
        if (t < NKER * NSB)
            g_cursor[t] = (t >> 2) * ZCAP + (t & 3) * SBCAP;
        if (t == 128) g_extra = 0;
    }

    float4* src4 = (float4*)(SCRATCH + (size_t)cellbase * C_DIM);
    float4  z4   = make_float4(0.f, 0.f, 0.f, 0.f);
    #pragma unroll
    for (int it = 0; it < 4; it++) {
        int i  = t + 256 * it;           // 0..1023
        int y  = i >> 4;
        int c4 = i & 15;
        float4 v = z4;
        if (s_t[y]) {
            v = src4[i];
            src4[i] = z4;                // re-zero consumed scratch row
        }
        *(float4*)&ts[y * 68 + 4 * c4] = v;
    }
    __syncthreads();

    int c  = t >> 2;                     // 0..63
    int gq = t & 3;
    float4* out4 = (float4*)out;
    // (b,c) plane = 16384 float4; x row = 64 float4; y-quarter = 16 float4
    size_t rowbase = ((size_t)(b * C_DIM + c)) * 16384 + x * 64 + yq * 16;
    #pragma unroll
    for (int it = 0; it < 4; it++) {
        int g = gq + 4 * it;             // 0..15 float4 within 64 y's
        float4 v;
        v.x = ts[(4 * g + 0) * 68 + c];
        v.y = ts[(4 * g + 1) * 68 + c];
        v.z = ts[(4 * g + 2) * 68 + c];
        v.w = ts[(4 * g + 3) * 68 + c];
        out4[rowbase + g] = v;
    }
}

// ---------------- launcher ---------------------------------------------------
extern "C" void kernel_launch(void* const* d_in, const int* in_sizes, int n_in,
                              void* d_out, int out_size) {
    const float* feat   = (const float*)d_in[0];
    const float* ker    = (const float*)d_in[1];
    const void*  coords = d_in[2];
    int N = in_sizes[0] / C_DIM;

    k_scatter<<<SGRID, STHREADS>>>(coords, N);
    k_compute<<<CGRID, 256>>>(feat, ker);
    k_transpose<<<4 * NBATCH * BEVX, 256>>>((float*)d_out);
}

// round 14
// speedup vs baseline: 1.4699x; 1.1488x over previous
#include <cuda_runtime.h>

#define C_DIM   64
#define NKER    32
#define BEVX    256
#define BEVY    256
#define NBATCH  4
#define CELLS   (NBATCH * BEVX * BEVY)      // 262144
#define MAXN    131072
#define PPB     128
#define ZCAP    4096                         // slots per z
#define NSB     4                            // sub-buckets per z
#define SBCAP   1024                         // slots per sub-bucket
#define NTILES  (NKER * NSB * (SBCAP / PPB)) // 1024
#define SGRID   128                          // scatter: 128 x 1024 >= N
#define STHREADS 1024

// ---------------- device state (zero/static-init at module load) ------------
// Replay invariant: touched map zero at scatter entry (transpose cleared it);
// cursors hold bucket bases (transpose block 0 reset them). Scratch rows for
// cells used THIS replay are zeroed by scatter itself (L2-hot for compute).
__device__ float4        g_scratch4[(size_t)CELLS * C_DIM / 4]; // 67 MB
__device__ unsigned char g_touched[CELLS];                      // zeroed
__device__ unsigned      g_sorted[MAXN];     // stale-ok (count-guarded)
__device__ unsigned      g_cells[MAXN];      // stale-ok (count-guarded)
#define SB4(z) (z)*ZCAP, (z)*ZCAP+SBCAP, (z)*ZCAP+2*SBCAP, (z)*ZCAP+3*SBCAP
__device__ int g_cursor[NKER * NSB] = {
    SB4(0),  SB4(1),  SB4(2),  SB4(3),  SB4(4),  SB4(5),  SB4(6),  SB4(7),
    SB4(8),  SB4(9),  SB4(10), SB4(11), SB4(12), SB4(13), SB4(14), SB4(15),
    SB4(16), SB4(17), SB4(18), SB4(19), SB4(20), SB4(21), SB4(22), SB4(23),
    SB4(24), SB4(25), SB4(26), SB4(27), SB4(28), SB4(29), SB4(30), SB4(31)
};

#define SCRATCH ((float*)g_scratch4)

// ---------------- packed fp32x2 helpers -------------------------------------
__device__ __forceinline__ unsigned long long pk(float x, float y) {
    unsigned long long r;
    asm("mov.b64 %0, {%1, %2};" : "=l"(r) : "f"(x), "f"(y));
    return r;
}
__device__ __forceinline__ float2 upk(unsigned long long v) {
    float2 r;
    asm("mov.b64 {%0, %1}, %2;" : "=f"(r.x), "=f"(r.y) : "l"(v));
    return r;
}
__device__ __forceinline__ unsigned long long ffma2(unsigned long long a,
                                                    unsigned long long b,
                                                    unsigned long long c) {
    unsigned long long d;
    asm("fma.rn.f32x2 %0, %1, %2, %3;" : "=l"(d) : "l"(a), "l"(b), "l"(c));
    return d;
}
__device__ __forceinline__ void red_v2(float* p, float a, float b) {
    asm volatile("red.global.add.v2.f32 [%0], {%1, %2};"
                 :: "l"(p), "f"(a), "f"(b) : "memory");
}

// ---------------- coord access ----------------------------------------------
// int64 coords: odd 32-bit words are zero high-words. int32: w[3]=b[0]=3 != 0.
__device__ __forceinline__ int detect64(const void* coords) {
    const unsigned* w = (const unsigned*)coords;
    return (w[1] | w[3] | w[5] | w[7]) == 0u;
}
__device__ __forceinline__ void ld_zcell(const void* coords, int n, int is64,
                                         int& z, int& cell) {
    int x, y, b;
    if (is64) {
        const long long* p = (const long long*)coords + 4ll * n;
        x = (int)p[0]; z = (int)p[1]; y = (int)p[2]; b = (int)p[3];
    } else {
        const int* p = (const int*)coords + 4 * n;
        x = p[0]; z = p[1]; y = p[2]; b = p[3];
    }
    // defensive clamps: malformed input can never index outside our arrays
    z    = z & (NKER - 1);
    cell = ((b * BEVX + x) * BEVY + y) & (CELLS - 1);
}

// ---------------- kernel 1: block-aggregated scatter + row zeroing ----------
// One point per thread. Local rank via smem counters, ONE global atomic per
// (block, z). Also zeroes each point's 256B scratch row (L2-warm for compute;
// duplicate zeroing of shared cells is benign — all zeroes, before any RED).
__global__ void __launch_bounds__(STHREADS) k_scatter(const void* __restrict__ coords,
                                                      int N) {
    __shared__ int s_cnt[NKER];
    __shared__ int s_base[NKER];
    __shared__ int s_is64;
    int tid = threadIdx.x;
    if (tid == 0) s_is64 = detect64(coords);
    if (tid < NKER) s_cnt[tid] = 0;
    __syncthreads();

    int sb = blockIdx.x & (NSB - 1);
    int n  = blockIdx.x * STHREADS + tid;
    bool valid = n < N;
    int z = 0, cell = 0, rank = 0;
    if (valid) {
        ld_zcell(coords, n, s_is64, z, cell);
        rank = atomicAdd(&s_cnt[z], 1);          // local rank (smem)
        // zero this cell's 256B scratch row (16 x STG.128)
        float4* row = (float4*)(SCRATCH + (size_t)cell * C_DIM);
        float4  z4  = make_float4(0.f, 0.f, 0.f, 0.f);
        #pragma unroll
        for (int i = 0; i < 16; i++) row[i] = z4;
    }
    __syncthreads();

    if (tid < NKER && s_cnt[tid] > 0)            // one global atomic per z
        s_base[tid] = atomicAdd(&g_cursor[tid * NSB + sb], s_cnt[tid]);
    __syncthreads();

    if (valid) {
        int pos = s_base[z] + rank;
        if (pos < (z * NSB + sb + 1) * SBCAP) {  // +8.8 sigma overflow guard
            g_sorted[pos]   = (unsigned)n;       // contiguous per-bucket runs
            g_cells[pos]    = (unsigned)cell;
            g_touched[cell] = 1;
        }
    }
}

// ---------------- kernel 2: tiled GEMM (smem kernel matrix) + RED.v2 --------
// Block = one 128-slot tile of one sub-bucket; valid count from final cursor.
// Warp owns 16 points, lane = channel-pair. smem = 32KB feat + 16KB kernel
// = 49152B exactly (static cap). Non-persistent: grid = NTILES.
__global__ void __launch_bounds__(256) k_compute(const float* __restrict__ feat,
                                                 const float* __restrict__ ker) {
    __shared__ float sfeat[128 * 64];                        // [p][c] 32KB
    __shared__ __align__(16) unsigned long long sk[64 * 32]; // [j][cpair] 16KB
    int tid  = threadIdx.x;
    int tile = blockIdx.x;
    int sbg  = tile >> 3;                // sub-bucket 0..127
    int tt   = tile & 7;                 // tile within sub-bucket
    int cnt  = g_cursor[sbg] - sbg * SBCAP;
    if (cnt > SBCAP) cnt = SBCAP;
    if (cnt < 0)     cnt = 0;
    int valid = cnt - tt * PPB;
    if (valid <= 0) return;              // uniform early exit for empty tiles
    if (valid > PPB) valid = PPB;

    int base = sbg * SBCAP + tt * PPB;

    { // kernel matrix: raw 16KB copy = 1024 float4 (4 chunks x 256 threads)
        const float4* kr = (const float4*)(ker + (size_t)(sbg >> 2) * 4096);
        float4* dst = (float4*)sk;
        dst[tid]       = kr[tid];
        dst[tid + 256] = kr[tid + 256];
        dst[tid + 512] = kr[tid + 512];
        dst[tid + 768] = kr[tid + 768];
    }

    // coalesced feature gather: 16 lanes cover one 256B row
    #pragma unroll
    for (int q = 0; q < 8; q++) {
        int idx = tid + 256 * q;
        int p   = idx >> 4;
        int c4  = idx & 15;
        float4 v = make_float4(0.f, 0.f, 0.f, 0.f);
        if (p < valid) {
            unsigned pv = __ldg(&g_sorted[base + p]) & (MAXN - 1u);
            v = *(const float4*)(feat + (size_t)pv * 64 + 4 * c4);
        }
        *(float4*)&sfeat[p * 64 + 4 * c4] = v;
    }
    __syncthreads();

    int lane = tid & 31;                 // channel pair (2*lane, 2*lane+1)
    int w    = tid >> 5;
    int p0   = w * 16;

    unsigned long long acc[16];
    #pragma unroll
    for (int s = 0; s < 16; s++) acc[s] = 0ull;

    #pragma unroll 2
    for (int j4 = 0; j4 < 16; j4++) {
        const unsigned long long* kr = sk + (4 * j4) * 32 + lane;
        unsigned long long k0 = kr[0], k1 = kr[32], k2 = kr[64], k3 = kr[96];
        #pragma unroll
        for (int s = 0; s < 16; s++) {
            float4 f4 = *(const float4*)&sfeat[(p0 + s) * 64 + 4 * j4]; // bcast
            unsigned long long a = acc[s];
            a = ffma2(pk(f4.x, f4.x), k0, a);
            a = ffma2(pk(f4.y, f4.y), k1, a);
            a = ffma2(pk(f4.z, f4.z), k2, a);
            a = ffma2(pk(f4.w, f4.w), k3, a);
            acc[s] = a;
        }
    }

    #pragma unroll
    for (int s = 0; s < 16; s++) {
        if (p0 + s < valid) {
            unsigned cell = __ldg(&g_cells[base + p0 + s]) & (CELLS - 1u);
            float2 v = upk(acc[s]);
            red_v2(SCRATCH + (size_t)cell * C_DIM + 2 * lane, v.x, v.y);
        }
    }
}

// ---------------- kernel 3: transpose + light cleanup -----------------------
// 256-thread blocks, 64y x 64c tile. Clears touched bytes it consumed; block 0
// resets cursors. NO scratch re-zero (scatter owns that next replay).
__global__ void __launch_bounds__(256) k_transpose(float* __restrict__ out) {
    __shared__ __align__(16) float ts[64 * 68];
    __shared__ unsigned char s_t[64];
    int bid = blockIdx.x;                // b(4) x x(256) x yq(4)
    int yq  = bid & 3;
    int x   = (bid >> 2) & 255;
    int b   = bid >> 10;
    int t   = threadIdx.x;

    int cellbase = (b * BEVX + x) * BEVY + yq * 64;
    if (t < 64) s_t[t] = g_touched[cellbase + t];
    __syncthreads();
    if (t < 64 && s_t[t]) g_touched[cellbase + t] = 0;   // clear for next replay
    if (bid == 0 && t < NKER * NSB)                       // reset cursors
        g_cursor[t] = (t >> 2) * ZCAP + (t & 3) * SBCAP;

    const float4* src4 = (const float4*)(SCRATCH + (size_t)cellbase * C_DIM);
    float4 z4 = make_float4(0.f, 0.f, 0.f, 0.f);
    #pragma unroll
    for (int it = 0; it < 4; it++) {
        int i  = t + 256 * it;           // 0..1023
        int y  = i >> 4;
        int c4 = i & 15;
        float4 v = z4;
        if (s_t[y]) v = src4[i];
        *(float4*)&ts[y * 68 + 4 * c4] = v;
    }
    __syncthreads();

    int c  = t >> 2;                     // 0..63
    int gq = t & 3;
    float4* out4 = (float4*)out;
    // (b,c) plane = 16384 float4; x row = 64 float4; y-quarter = 16 float4
    size_t rowbase = ((size_t)(b * C_DIM + c)) * 16384 + x * 64 + yq * 16;
    #pragma unroll
    for (int it = 0; it < 4; it++) {
        int g = gq + 4 * it;             // 0..15 float4 within 64 y's
        float4 v;
        v.x = ts[(4 * g + 0) * 68 + c];
        v.y = ts[(4 * g + 1) * 68 + c];
        v.z = ts[(4 * g + 2) * 68 + c];
        v.w = ts[(4 * g + 3) * 68 + c];
        out4[rowbase + g] = v;
    }
}

// ---------------- launcher ---------------------------------------------------
extern "C" void kernel_launch(void* const* d_in, const int* in_sizes, int n_in,
                              void* d_out, int out_size) {
    const float* feat   = (const float*)d_in[0];
    const float* ker    = (const float*)d_in[1];
    const void*  coords = d_in[2];
    int N = in_sizes[0] / C_DIM;

    k_scatter<<<SGRID, STHREADS>>>(coords, N);
    k_compute<<<NTILES, 256>>>(feat, ker);
    k_transpose<<<4 * NBATCH * BEVX, 256>>>((float*)d_out);
}

// round 15
// speedup vs baseline: 1.7195x; 1.1698x over previous
#include <cuda_runtime.h>

#define C_DIM   64
#define NKER    32
#define BEVX    256
#define BEVY    256
#define NBATCH  4
#define CELLS   (NBATCH * BEVX * BEVY)      // 262144
#define MAXN    131072
#define PPB     128
#define ZCAP    4096                         // slots per z
#define NSB     4                            // sub-buckets per z
#define SBCAP   1024                         // slots per sub-bucket
#define NTILES  (NKER * NSB * (SBCAP / PPB)) // 1024
#define SGRID   128                          // scatter: 128 x 1024 >= N
#define STHREADS 1024

// ---------------- device state (zero/static-init at module load) ------------
// Replay invariant: touched map zero at scatter entry (transpose cleared it);
// cursors hold bucket bases (transpose block 0 reset them). Scratch rows for
// cells used THIS replay are zeroed by scatter itself (L2-hot for compute).
__device__ float4        g_scratch4[(size_t)CELLS * C_DIM / 4]; // 67 MB
__device__ unsigned char g_touched[CELLS];                      // zeroed
__device__ unsigned      g_sorted[MAXN];     // stale-ok (count-guarded)
__device__ unsigned      g_cells[MAXN];      // stale-ok (count-guarded)
#define SB4(z) (z)*ZCAP, (z)*ZCAP+SBCAP, (z)*ZCAP+2*SBCAP, (z)*ZCAP+3*SBCAP
__device__ int g_cursor[NKER * NSB] = {
    SB4(0),  SB4(1),  SB4(2),  SB4(3),  SB4(4),  SB4(5),  SB4(6),  SB4(7),
    SB4(8),  SB4(9),  SB4(10), SB4(11), SB4(12), SB4(13), SB4(14), SB4(15),
    SB4(16), SB4(17), SB4(18), SB4(19), SB4(20), SB4(21), SB4(22), SB4(23),
    SB4(24), SB4(25), SB4(26), SB4(27), SB4(28), SB4(29), SB4(30), SB4(31)
};

#define SCRATCH ((float*)g_scratch4)

// ---------------- packed fp32x2 helpers -------------------------------------
__device__ __forceinline__ unsigned long long pk(float x, float y) {
    unsigned long long r;
    asm("mov.b64 %0, {%1, %2};" : "=l"(r) : "f"(x), "f"(y));
    return r;
}
__device__ __forceinline__ float2 upk(unsigned long long v) {
    float2 r;
    asm("mov.b64 {%0, %1}, %2;" : "=f"(r.x), "=f"(r.y) : "l"(v));
    return r;
}
__device__ __forceinline__ unsigned long long ffma2(unsigned long long a,
                                                    unsigned long long b,
                                                    unsigned long long c) {
    unsigned long long d;
    asm("fma.rn.f32x2 %0, %1, %2, %3;" : "=l"(d) : "l"(a), "l"(b), "l"(c));
    return d;
}
__device__ __forceinline__ void red_v2(float* p, float a, float b) {
    asm volatile("red.global.add.v2.f32 [%0], {%1, %2};"
                 :: "l"(p), "f"(a), "f"(b) : "memory");
}

// ---------------- coord access ----------------------------------------------
// int64 coords: odd 32-bit words are zero high-words. int32: w[3]=b[0]=3 != 0.
__device__ __forceinline__ int detect64(const void* coords) {
    const unsigned* w = (const unsigned*)coords;
    return (w[1] | w[3] | w[5] | w[7]) == 0u;
}
__device__ __forceinline__ void ld_zcell(const void* coords, int n, int is64,
                                         int& z, int& cell) {
    int x, y, b;
    if (is64) {
        const long long* p = (const long long*)coords + 4ll * n;
        x = (int)p[0]; z = (int)p[1]; y = (int)p[2]; b = (int)p[3];
    } else {
        const int* p = (const int*)coords + 4 * n;
        x = p[0]; z = p[1]; y = p[2]; b = p[3];
    }
    // defensive clamps: malformed input can never index outside our arrays
    z    = z & (NKER - 1);
    cell = ((b * BEVX + x) * BEVY + y) & (CELLS - 1);
}

// ---------------- kernel 1: block-aggregated scatter + cooperative zeroing --
// One point per thread. Local rank via smem counters, ONE global atomic per
// (block, z). Row zeroing is warp-cooperative: all 32 lanes jointly zero one
// 256B row per iteration (single coalesced STG.64 wavefront), instead of each
// lane serially writing its own scattered row.
__global__ void __launch_bounds__(STHREADS) k_scatter(const void* __restrict__ coords,
                                                      int N) {
    __shared__ int s_cnt[NKER];
    __shared__ int s_base[NKER];
    __shared__ int s_is64;
    int tid  = threadIdx.x;
    int lane = tid & 31;
    if (tid == 0) s_is64 = detect64(coords);
    if (tid < NKER) s_cnt[tid] = 0;
    __syncthreads();

    int sb = blockIdx.x & (NSB - 1);
    int n  = blockIdx.x * STHREADS + tid;
    bool valid = n < N;
    int z = 0, cell = 0, rank = 0;
    if (valid) {
        ld_zcell(coords, n, s_is64, z, cell);
        rank = atomicAdd(&s_cnt[z], 1);          // local rank (smem)
    }

    // warp-cooperative zero of each valid lane's 256B scratch row
    {
        unsigned m = __ballot_sync(0xffffffffu, valid);
        float2* z2base = (float2*)SCRATCH;
        float2  zz = make_float2(0.f, 0.f);
        #pragma unroll 4
        for (int s = 0; s < 32; s++) {
            if ((m >> s) & 1u) {
                unsigned c = __shfl_sync(0xffffffffu, (unsigned)cell, s);
                z2base[(size_t)c * 32 + lane] = zz;   // 32 lanes = one 256B row
            }
        }
    }
    __syncthreads();

    if (tid < NKER && s_cnt[tid] > 0)            // one global atomic per z
        s_base[tid] = atomicAdd(&g_cursor[tid * NSB + sb], s_cnt[tid]);
    __syncthreads();

    if (valid) {
        int pos = s_base[z] + rank;
        if (pos < (z * NSB + sb + 1) * SBCAP) {  // +8.8 sigma overflow guard
            g_sorted[pos]   = (unsigned)n;       // contiguous per-bucket runs
            g_cells[pos]    = (unsigned)cell;
            g_touched[cell] = 1;
        }
    }
}

// ---------------- kernel 2: tiled GEMM (smem kernel matrix) + RED.v2 --------
// Block = one 128-slot tile of one sub-bucket; valid count from final cursor.
// Warp owns 16 points, lane = channel-pair. smem = 32KB feat + 16KB kernel
// = 49152B exactly (static cap). Non-persistent: grid = NTILES.
__global__ void __launch_bounds__(256) k_compute(const float* __restrict__ feat,
                                                 const float* __restrict__ ker) {
    __shared__ float sfeat[128 * 64];                        // [p][c] 32KB
    __shared__ __align__(16) unsigned long long sk[64 * 32]; // [j][cpair] 16KB
    int tid  = threadIdx.x;
    int tile = blockIdx.x;
    int sbg  = tile >> 3;                // sub-bucket 0..127
    int tt   = tile & 7;                 // tile within sub-bucket
    int cnt  = g_cursor[sbg] - sbg * SBCAP;
    if (cnt > SBCAP) cnt = SBCAP;
    if (cnt < 0)     cnt = 0;
    int valid = cnt - tt * PPB;
    if (valid <= 0) return;              // uniform early exit for empty tiles
    if (valid > PPB) valid = PPB;

    int base = sbg * SBCAP + tt * PPB;

    { // kernel matrix: raw 16KB copy = 1024 float4 (4 chunks x 256 threads)
        const float4* kr = (const float4*)(ker + (size_t)(sbg >> 2) * 4096);
        float4* dst = (float4*)sk;
        dst[tid]       = kr[tid];
        dst[tid + 256] = kr[tid + 256];
        dst[tid + 512] = kr[tid + 512];
        dst[tid + 768] = kr[tid + 768];
    }

    // coalesced feature gather: 16 lanes cover one 256B row
    #pragma unroll
    for (int q = 0; q < 8; q++) {
        int idx = tid + 256 * q;
        int p   = idx >> 4;
        int c4  = idx & 15;
        float4 v = make_float4(0.f, 0.f, 0.f, 0.f);
        if (p < valid) {
            unsigned pv = __ldg(&g_sorted[base + p]) & (MAXN - 1u);
            v = *(const float4*)(feat + (size_t)pv * 64 + 4 * c4);
        }
        *(float4*)&sfeat[p * 64 + 4 * c4] = v;
    }
    __syncthreads();

    int lane = tid & 31;                 // channel pair (2*lane, 2*lane+1)
    int w    = tid >> 5;
    int p0   = w * 16;

    unsigned long long acc[16];
    #pragma unroll
    for (int s = 0; s < 16; s++) acc[s] = 0ull;

    #pragma unroll 2
    for (int j4 = 0; j4 < 16; j4++) {
        const unsigned long long* kr = sk + (4 * j4) * 32 + lane;
        unsigned long long k0 = kr[0], k1 = kr[32], k2 = kr[64], k3 = kr[96];
        #pragma unroll
        for (int s = 0; s < 16; s++) {
            float4 f4 = *(const float4*)&sfeat[(p0 + s) * 64 + 4 * j4]; // bcast
            unsigned long long a = acc[s];
            a = ffma2(pk(f4.x, f4.x), k0, a);
            a = ffma2(pk(f4.y, f4.y), k1, a);
            a = ffma2(pk(f4.z, f4.z), k2, a);
            a = ffma2(pk(f4.w, f4.w), k3, a);
            acc[s] = a;
        }
    }

    #pragma unroll
    for (int s = 0; s < 16; s++) {
        if (p0 + s < valid) {
            unsigned cell = __ldg(&g_cells[base + p0 + s]) & (CELLS - 1u);
            float2 v = upk(acc[s]);
            red_v2(SCRATCH + (size_t)cell * C_DIM + 2 * lane, v.x, v.y);
        }
    }
}

// ---------------- kernel 3: transpose + light cleanup -----------------------
// 256-thread blocks, 64y x 64c tile. Clears touched bytes it consumed; block 0
// resets cursors. NO scratch re-zero (scatter owns that next replay).
__global__ void __launch_bounds__(256) k_transpose(float* __restrict__ out) {
    __shared__ __align__(16) float ts[64 * 68];
    __shared__ unsigned char s_t[64];
    int bid = blockIdx.x;                // b(4) x x(256) x yq(4)
    int yq  = bid & 3;
    int x   = (bid >> 2) & 255;
    int b   = bid >> 10;
    int t   = threadIdx.x;

    int cellbase = (b * BEVX + x) * BEVY + yq * 64;
    if (t < 64) s_t[t] = g_touched[cellbase + t];
    __syncthreads();
    if (t < 64 && s_t[t]) g_touched[cellbase + t] = 0;   // clear for next replay
    if (bid == 0 && t < NKER * NSB)                       // reset cursors
        g_cursor[t] = (t >> 2) * ZCAP + (t & 3) * SBCAP;

    const float4* src4 = (const float4*)(SCRATCH + (size_t)cellbase * C_DIM);
    float4 z4 = make_float4(0.f, 0.f, 0.f, 0.f);
    #pragma unroll
    for (int it = 0; it < 4; it++) {
        int i  = t + 256 * it;           // 0..1023
        int y  = i >> 4;
        int c4 = i & 15;
        float4 v = z4;
        if (s_t[y]) v = src4[i];
        *(float4*)&ts[y * 68 + 4 * c4] = v;
    }
    __syncthreads();

    int c  = t >> 2;                     // 0..63
    int gq = t & 3;
    float4* out4 = (float4*)out;
    // (b,c) plane = 16384 float4; x row = 64 float4; y-quarter = 16 float4
    size_t rowbase = ((size_t)(b * C_DIM + c)) * 16384 + x * 64 + yq * 16;
    #pragma unroll
    for (int it = 0; it < 4; it++) {
        int g = gq + 4 * it;             // 0..15 float4 within 64 y's
        float4 v;
        v.x = ts[(4 * g + 0) * 68 + c];
        v.y = ts[(4 * g + 1) * 68 + c];
        v.z = ts[(4 * g + 2) * 68 + c];
        v.w = ts[(4 * g + 3) * 68 + c];
        out4[rowbase + g] = v;
    }
}

// ---------------- launcher ---------------------------------------------------
extern "C" void kernel_launch(void* const* d_in, const int* in_sizes, int n_in,
                              void* d_out, int out_size) {
    const float* feat   = (const float*)d_in[0];
    const float* ker    = (const float*)d_in[1];
    const void*  coords = d_in[2];
    int N = in_sizes[0] / C_DIM;

    k_scatter<<<SGRID, STHREADS>>>(coords, N);
    k_compute<<<NTILES, 256>>>(feat, ker);
    k_transpose<<<4 * NBATCH * BEVX, 256>>>((float*)d_out);
}

// round 16
// speedup vs baseline: 1.7214x; 1.0011x over previous
#include <cuda_runtime.h>

#define C_DIM   64
#define NKER    32
#define BEVX    256
#define BEVY    256
#define NBATCH  4
#define CELLS   (NBATCH * BEVX * BEVY)      // 262144
#define MAXN    131072
#define PPB     128
#define ZCAP    4096                         // slots per z
#define NSB     4                            // sub-buckets per z
#define SBCAP   1024                         // slots per sub-bucket
#define NTILES  (NKER * NSB * (SBCAP / PPB)) // 1024
#define SGRID   128                          // scatter: 128 x 1024 >= N
#define STHREADS 1024

// ---------------- device state (zero/static-init at module load) ------------
// Replay invariant: touched map zero at scatter entry (transpose cleared it);
// cursors hold bucket bases (transpose block 0 reset them). Scratch rows for
// cells used THIS replay are zeroed by scatter itself (L2-hot for compute).
__device__ float4        g_scratch4[(size_t)CELLS * C_DIM / 4]; // 67 MB
__device__ unsigned char g_touched[CELLS];                      // zeroed
__device__ unsigned      g_sorted[MAXN];     // stale-ok (count-guarded)
__device__ unsigned      g_cells[MAXN];      // stale-ok (count-guarded)
#define SB4(z) (z)*ZCAP, (z)*ZCAP+SBCAP, (z)*ZCAP+2*SBCAP, (z)*ZCAP+3*SBCAP
__device__ int g_cursor[NKER * NSB] = {
    SB4(0),  SB4(1),  SB4(2),  SB4(3),  SB4(4),  SB4(5),  SB4(6),  SB4(7),
    SB4(8),  SB4(9),  SB4(10), SB4(11), SB4(12), SB4(13), SB4(14), SB4(15),
    SB4(16), SB4(17), SB4(18), SB4(19), SB4(20), SB4(21), SB4(22), SB4(23),
    SB4(24), SB4(25), SB4(26), SB4(27), SB4(28), SB4(29), SB4(30), SB4(31)
};

#define SCRATCH ((float*)g_scratch4)

// ---------------- packed fp32x2 helpers -------------------------------------
__device__ __forceinline__ unsigned long long pk(float x, float y) {
    unsigned long long r;
    asm("mov.b64 %0, {%1, %2};" : "=l"(r) : "f"(x), "f"(y));
    return r;
}
__device__ __forceinline__ float2 upk(unsigned long long v) {
    float2 r;
    asm("mov.b64 {%0, %1}, %2;" : "=f"(r.x), "=f"(r.y) : "l"(v));
    return r;
}
__device__ __forceinline__ unsigned long long ffma2(unsigned long long a,
                                                    unsigned long long b,
                                                    unsigned long long c) {
    unsigned long long d;
    asm("fma.rn.f32x2 %0, %1, %2, %3;" : "=l"(d) : "l"(a), "l"(b), "l"(c));
    return d;
}
__device__ __forceinline__ void red_v2(float* p, float a, float b) {
    asm volatile("red.global.add.v2.f32 [%0], {%1, %2};"
                 :: "l"(p), "f"(a), "f"(b) : "memory");
}

// ---------------- coord access ----------------------------------------------
// int64 coords: odd 32-bit words are zero high-words. int32: w[3]=b[0]=3 != 0.
__device__ __forceinline__ int detect64(const void* coords) {
    const unsigned* w = (const unsigned*)coords;
    return (w[1] | w[3] | w[5] | w[7]) == 0u;
}
__device__ __forceinline__ void ld_zcell(const void* coords, int n, int is64,
                                         int& z, int& cell) {
    int x, y, b;
    if (is64) {
        const long long* p = (const long long*)coords + 4ll * n;
        x = (int)p[0]; z = (int)p[1]; y = (int)p[2]; b = (int)p[3];
    } else {
        const int* p = (const int*)coords + 4 * n;
        x = p[0]; z = p[1]; y = p[2]; b = p[3];
    }
    // defensive clamps: malformed input can never index outside our arrays
    z    = z & (NKER - 1);
    cell = ((b * BEVX + x) * BEVY + y) & (CELLS - 1);
}

// ---------------- kernel 1: block-aggregated scatter + paired row zeroing ---
// One point per thread. Local rank via smem counters, ONE global atomic per
// (block, z). Row zeroing: warp zeroes TWO 256B rows per iteration with
// full-width float4 stores (lanes 0-15 -> row A, lanes 16-31 -> row B).
__global__ void __launch_bounds__(STHREADS) k_scatter(const void* __restrict__ coords,
                                                      int N) {
    __shared__ int s_cnt[NKER];
    __shared__ int s_base[NKER];
    __shared__ int s_is64;
    int tid  = threadIdx.x;
    int lane = tid & 31;
    if (tid == 0) s_is64 = detect64(coords);
    if (tid < NKER) s_cnt[tid] = 0;
    __syncthreads();

    int sb = blockIdx.x & (NSB - 1);
    int n  = blockIdx.x * STHREADS + tid;
    bool valid = n < N;
    int z = 0, cell = 0, rank = 0;
    if (valid) {
        ld_zcell(coords, n, s_is64, z, cell);
        rank = atomicAdd(&s_cnt[z], 1);          // local rank (smem)
    }

    // warp-cooperative zero: two 256B rows per iteration, STG.128 per lane
    {
        unsigned m = __ballot_sync(0xffffffffu, valid);
        float4* z4base = (float4*)SCRATCH;
        float4  zz = make_float4(0.f, 0.f, 0.f, 0.f);
        int  half  = lane >> 4;                  // 0: row A, 1: row B
        int  sub   = lane & 15;
        #pragma unroll 4
        for (int s = 0; s < 32; s += 2) {
            unsigned c0 = __shfl_sync(0xffffffffu, (unsigned)cell, s);
            unsigned c1 = __shfl_sync(0xffffffffu, (unsigned)cell, s + 1);
            unsigned cc = half ? c1 : c0;
            if ((m >> (s + half)) & 1u)
                z4base[(size_t)cc * 16 + sub] = zz;  // 16 lanes = one 256B row
        }
    }
    __syncthreads();

    if (tid < NKER && s_cnt[tid] > 0)            // one global atomic per z
        s_base[tid] = atomicAdd(&g_cursor[tid * NSB + sb], s_cnt[tid]);
    __syncthreads();

    if (valid) {
        int pos = s_base[z] + rank;
        if (pos < (z * NSB + sb + 1) * SBCAP) {  // +8.8 sigma overflow guard
            g_sorted[pos]   = (unsigned)n;       // contiguous per-bucket runs
            g_cells[pos]    = (unsigned)cell;
            g_touched[cell] = 1;
        }
    }
}

// ---------------- kernel 2: tiled GEMM (smem kernel matrix) + RED.v2 --------
// Block = one 128-slot tile of one sub-bucket; valid count from final cursor.
// Warp owns 16 points, lane = channel-pair. smem = 32KB feat + 16KB kernel
// = 49152B exactly (static cap). Non-persistent: grid = NTILES.
__global__ void __launch_bounds__(256) k_compute(const float* __restrict__ feat,
                                                 const float* __restrict__ ker) {
    __shared__ float sfeat[128 * 64];                        // [p][c] 32KB
    __shared__ __align__(16) unsigned long long sk[64 * 32]; // [j][cpair] 16KB
    int tid  = threadIdx.x;
    int tile = blockIdx.x;
    int sbg  = tile >> 3;                // sub-bucket 0..127
    int tt   = tile & 7;                 // tile within sub-bucket
    int cnt  = g_cursor[sbg] - sbg * SBCAP;
    if (cnt > SBCAP) cnt = SBCAP;
    if (cnt < 0)     cnt = 0;
    int valid = cnt - tt * PPB;
    if (valid <= 0) return;              // uniform early exit for empty tiles
    if (valid > PPB) valid = PPB;

    int base = sbg * SBCAP + tt * PPB;

    { // kernel matrix: raw 16KB copy = 1024 float4 (4 chunks x 256 threads)
        const float4* kr = (const float4*)(ker + (size_t)(sbg >> 2) * 4096);
        float4* dst = (float4*)sk;
        dst[tid]       = kr[tid];
        dst[tid + 256] = kr[tid + 256];
        dst[tid + 512] = kr[tid + 512];
        dst[tid + 768] = kr[tid + 768];
    }

    // coalesced feature gather: 16 lanes cover one 256B row
    #pragma unroll
    for (int q = 0; q < 8; q++) {
        int idx = tid + 256 * q;
        int p   = idx >> 4;
        int c4  = idx & 15;
        float4 v = make_float4(0.f, 0.f, 0.f, 0.f);
        if (p < valid) {
            unsigned pv = __ldg(&g_sorted[base + p]) & (MAXN - 1u);
            v = *(const float4*)(feat + (size_t)pv * 64 + 4 * c4);
        }
        *(float4*)&sfeat[p * 64 + 4 * c4] = v;
    }
    __syncthreads();

    int lane = tid & 31;                 // channel pair (2*lane, 2*lane+1)
    int w    = tid >> 5;
    int p0   = w * 16;

    unsigned long long acc[16];
    #pragma unroll
    for (int s = 0; s < 16; s++) acc[s] = 0ull;

    #pragma unroll 2
    for (int j4 = 0; j4 < 16; j4++) {
        const unsigned long long* kr = sk + (4 * j4) * 32 + lane;
        unsigned long long k0 = kr[0], k1 = kr[32], k2 = kr[64], k3 = kr[96];
        #pragma unroll
        for (int s = 0; s < 16; s++) {
            float4 f4 = *(const float4*)&sfeat[(p0 + s) * 64 + 4 * j4]; // bcast
            unsigned long long a = acc[s];
            a = ffma2(pk(f4.x, f4.x), k0, a);
            a = ffma2(pk(f4.y, f4.y), k1, a);
            a = ffma2(pk(f4.z, f4.z), k2, a);
            a = ffma2(pk(f4.w, f4.w), k3, a);
            acc[s] = a;
        }
    }

    #pragma unroll
    for (int s = 0; s < 16; s++) {
        if (p0 + s < valid) {
            unsigned cell = __ldg(&g_cells[base + p0 + s]) & (CELLS - 1u);
            float2 v = upk(acc[s]);
            red_v2(SCRATCH + (size_t)cell * C_DIM + 2 * lane, v.x, v.y);
        }
    }
}

// ---------------- kernel 3: transpose + light cleanup -----------------------
// 256-thread blocks, 64y x 64c tile. Clears touched bytes it consumed; block 0
// resets cursors. NO scratch re-zero (scatter owns that next replay).
__global__ void __launch_bounds__(256) k_transpose(float* __restrict__ out) {
    __shared__ __align__(16) float ts[64 * 68];
    __shared__ unsigned char s_t[64];
    int bid = blockIdx.x;                // b(4) x x(256) x yq(4)
    int yq  = bid & 3;
    int x   = (bid >> 2) & 255;
    int b   = bid >> 10;
    int t   = threadIdx.x;

    int cellbase = (b * BEVX + x) * BEVY + yq * 64;
    if (t < 64) s_t[t] = g_touched[cellbase + t];
    __syncthreads();
    if (t < 64 && s_t[t]) g_touched[cellbase + t] = 0;   // clear for next replay
    if (bid == 0 && t < NKER * NSB)                       // reset cursors
        g_cursor[t] = (t >> 2) * ZCAP + (t & 3) * SBCAP;

    const float4* src4 = (const float4*)(SCRATCH + (size_t)cellbase * C_DIM);
    float4 z4 = make_float4(0.f, 0.f, 0.f, 0.f);
    #pragma unroll
    for (int it = 0; it < 4; it++) {
        int i  = t + 256 * it;           // 0..1023
        int y  = i >> 4;
        int c4 = i & 15;
        float4 v = z4;
        if (s_t[y]) v = src4[i];
        *(float4*)&ts[y * 68 + 4 * c4] = v;
    }
    __syncthreads();

    int c  = t >> 2;                     // 0..63
    int gq = t & 3;
    float4* out4 = (float4*)out;
    // (b,c) plane = 16384 float4; x row = 64 float4; y-quarter = 16 float4
    size_t rowbase = ((size_t)(b * C_DIM + c)) * 16384 + x * 64 + yq * 16;
    #pragma unroll
    for (int it = 0; it < 4; it++) {
        int g = gq + 4 * it;             // 0..15 float4 within 64 y's
        float4 v;
        v.x = ts[(4 * g + 0) * 68 + c];
        v.y = ts[(4 * g + 1) * 68 + c];
        v.z = ts[(4 * g + 2) * 68 + c];
        v.w = ts[(4 * g + 3) * 68 + c];
        out4[rowbase + g] = v;
    }
}

// ---------------- launcher ---------------------------------------------------
extern "C" void kernel_launch(void* const* d_in, const int* in_sizes, int n_in,
                              void* d_out, int out_size) {
    const float* feat   = (const float*)d_in[0];
    const float* ker    = (const float*)d_in[1];
    const void*  coords = d_in[2];
    int N = in_sizes[0] / C_DIM;

    k_scatter<<<SGRID, STHREADS>>>(coords, N);
    k_compute<<<NTILES, 256>>>(feat, ker);
    k_transpose<<<4 * NBATCH * BEVX, 256>>>((float*)d_out);
}